// round 3
// baseline (speedup 1.0000x reference)
#include <cuda_runtime.h>
#include <cuda_bf16.h>

#define B_TOTAL        65536
#define N_K            64
#define ROW_FLOATS     (N_K * 3)          // 192 floats per row per tensor
#define DEGREE         3
#define SAMPLES        20
#define ROWS_PER_BLOCK 8
#define THREADS        (ROWS_PER_BLOCK * SAMPLES)  // 160
#define NBLOCKS        (B_TOTAL / ROWS_PER_BLOCK)  // 8192
#define KF_LEN         68                 // 4 zeros + 64 knots

__device__ double        g_sum;     // zero-init; reset by last block each run
__device__ unsigned int  g_count;   // zero-init; reset by last block each run

// De Boor sample given padded kf row (kf[i] = 0 for i<4, knots[i-4] else)
// and float2 coeff row. i0 = interval index (s-3).
__device__ __forceinline__ void deboor_eval(const float*  __restrict__ kf,
                                            const float2* __restrict__ cxy,
                                            float t, int i0,
                                            float& ox, float& oy)
{
    float kfv[7];
#pragma unroll
    for (int m = 1; m < 7; m++) kfv[m] = kf[i0 + m];   // kfv[0] never used

    float px[4], py[4];
#pragma unroll
    for (int k = 0; k < 4; k++) {
        float2 c = cxy[i0 + k];
        px[k] = c.x; py[k] = c.y;
    }

#pragma unroll
    for (int l = 1; l <= DEGREE; l++) {
#pragma unroll
        for (int k = 3; k >= 1; k--) {
            if (k < l) break;
            float ki = kfv[k];
            float kj = kfv[k + 4 - l];
            float denom = kj - ki;
            float alpha = (denom != 0.0f) ? __fdividef(t - ki, denom) : 0.0f;
            px[k] = fmaf(alpha, px[k] - px[k - 1], px[k - 1]);
            py[k] = fmaf(alpha, py[k] - py[k - 1], py[k - 1]);
        }
    }
    ox = px[3];   // homogeneous weight stays exactly 1 -> no division
    oy = py[3];
}

// Branchless count of knots <= t, knots live at kf[4..63+4].
__device__ __forceinline__ int knot_search(const float* __restrict__ kf, float t)
{
    int a = 0;
#pragma unroll
    for (int step = 32; step > 0; step >>= 1) {
        int ca = a + step;
        if (ca <= 60 && kf[ca + 3] <= t) a = ca;
    }
    return a;
}

__global__ __launch_bounds__(THREADS)
void bspline_loss_fused(const float* __restrict__ pred,
                        const float* __restrict__ tru,
                        float* __restrict__ out)
{
    __shared__ float  s_kf [2][ROWS_PER_BLOCK][KF_LEN];
    __shared__ float2 s_cxy[2][ROWS_PER_BLOCK][N_K];

    // Zero the 4-slot kf padding: 2 tensors x 8 rows x 4 = 64 slots.
    if (threadIdx.x < 2 * ROWS_PER_BLOCK * 4) {
        int tsel = threadIdx.x >> 5;           // 0..1
        int r    = (threadIdx.x >> 2) & 7;     // 0..7
        int z    = threadIdx.x & 3;            // 0..3
        s_kf[tsel][r][z] = 0.0f;
    }

    // Coalesced float4 loads, scattered into SoA smem.
    {
        const size_t base = (size_t)blockIdx.x * ROWS_PER_BLOCK * ROW_FLOATS;
        const float4* gp = reinterpret_cast<const float4*>(pred + base);
        const float4* gt = reinterpret_cast<const float4*>(tru + base);
        const int n4 = ROWS_PER_BLOCK * ROW_FLOATS / 4;   // 384
        for (int i4 = threadIdx.x; i4 < n4; i4 += THREADS) {
            int row = i4 / 48;                 // 48 float4 per row
            int rem = (i4 - row * 48) * 4;     // float offset within row, 0..188
            float4 vp = gp[i4];
            float4 vt = gt[i4];
            float ap[4] = {vp.x, vp.y, vp.z, vp.w};
            float at[4] = {vt.x, vt.y, vt.z, vt.w};
#pragma unroll
            for (int q = 0; q < 4; q++) {
                int pos = rem + q;
                int i   = pos / 3;
                int c   = pos - 3 * i;
                if (c == 0) {
                    s_kf[0][row][4 + i] = ap[q];
                    s_kf[1][row][4 + i] = at[q];
                } else if (c == 1) {
                    s_cxy[0][row][i].x = ap[q];
                    s_cxy[1][row][i].x = at[q];
                } else {
                    s_cxy[0][row][i].y = ap[q];
                    s_cxy[1][row][i].y = at[q];
                }
            }
        }
    }
    __syncthreads();

    const int row = threadIdx.x / SAMPLES;
    const int j   = threadIdx.x % SAMPLES;

    const float*  kp = &s_kf [0][row][0];
    const float*  kt = &s_kf [1][row][0];
    const float2* cp = &s_cxy[0][row][0];
    const float2* ct = &s_cxy[1][row][0];

    const float frac = (float)j / 19.0f;
    const float tp = frac * kp[64];            // high = knots[60] = kf[64], low = 0
    const float tt = frac * kt[64];

    const int i0p = knot_search(kp, tp);
    const int i0t = knot_search(kt, tt);

    float pxv, pyv, txv, tyv;
    deboor_eval(kp, cp, tp, i0p, pxv, pyv);
    deboor_eval(kt, ct, tt, i0t, txv, tyv);

    float dx = pxv - txv;
    float dy = pyv - tyv;
    float val = fmaf(dx, dx, dy * dy);

    // Warp reduce (5 full warps).
#pragma unroll
    for (int o = 16; o > 0; o >>= 1)
        val += __shfl_down_sync(0xFFFFFFFFu, val, o);

    __shared__ float warpsum[THREADS / 32];
    const int wid  = threadIdx.x >> 5;
    const int lane = threadIdx.x & 31;
    if (lane == 0) warpsum[wid] = val;
    __syncthreads();

    if (threadIdx.x == 0) {
        double tot = 0.0;
#pragma unroll
        for (int w = 0; w < THREADS / 32; w++) tot += (double)warpsum[w];
        atomicAdd(&g_sum, tot);
        __threadfence();
        unsigned int ticket = atomicAdd(&g_count, 1u);
        if (ticket == NBLOCKS - 1) {
            out[0] = (float)(g_sum / (double)((long long)B_TOTAL * SAMPLES));
            g_sum = 0.0;
            __threadfence();
            g_count = 0u;
        }
    }
}

extern "C" void kernel_launch(void* const* d_in, const int* in_sizes, int n_in,
                              void* d_out, int out_size)
{
    const float* pred = (const float*)d_in[0];
    const float* tru  = (const float*)d_in[1];
    float* out = (float*)d_out;

    bspline_loss_fused<<<NBLOCKS, THREADS>>>(pred, tru, out);
}

// round 4
// speedup vs baseline: 1.4078x; 1.4078x over previous
#include <cuda_runtime.h>
#include <cuda_bf16.h>

#define B_TOTAL        65536
#define N_K            64
#define ROW_FLOATS     (N_K * 3)          // 192 floats per row per tensor
#define DEGREE         3
#define SAMPLES        20
#define ROWS_PER_BLOCK 8
#define THREADS        (ROWS_PER_BLOCK * SAMPLES)  // 160
#define NBLOCKS        (B_TOTAL / ROWS_PER_BLOCK)  // 8192
#define KF_LEN         68                 // 4 zeros + 64 knots (stride 68 ≡ 4 mod 32 banks)
#define CXY_LEN        66                 // 64 coeffs + 2 pad  (132 words ≡ 4 mod 32 banks)

__device__ double        g_sum;     // zero-init; reset by last block each run
__device__ unsigned int  g_count;   // zero-init; reset by last block each run

// De Boor sample given padded kf row (kf[i]=0 for i<4, knots[i-4] else)
// and float2 coeff row. i0 = interval index (s-3).
__device__ __forceinline__ void deboor_eval(const float*  __restrict__ kf,
                                            const float2* __restrict__ cxy,
                                            float t, int i0,
                                            float& ox, float& oy)
{
    float kfv[7];
#pragma unroll
    for (int m = 1; m < 7; m++) kfv[m] = kf[i0 + m];   // kfv[0] never used

    float px[4], py[4];
#pragma unroll
    for (int k = 0; k < 4; k++) {
        float2 c = cxy[i0 + k];
        px[k] = c.x; py[k] = c.y;
    }

#pragma unroll
    for (int l = 1; l <= DEGREE; l++) {
#pragma unroll
        for (int k = 3; k >= 1; k--) {
            if (k < l) break;
            float ki = kfv[k];
            float kj = kfv[k + 4 - l];
            float denom = kj - ki;
            float alpha = (denom != 0.0f) ? __fdividef(t - ki, denom) : 0.0f;
            px[k] = fmaf(alpha, px[k] - px[k - 1], px[k - 1]);
            py[k] = fmaf(alpha, py[k] - py[k - 1], py[k - 1]);
        }
    }
    ox = px[3];   // homogeneous weight stays exactly 1 -> no division
    oy = py[3];
}

// Branchless count of knots <= t; knots live at kf[4..67].
__device__ __forceinline__ int knot_search(const float* __restrict__ kf, float t)
{
    int a = 0;
#pragma unroll
    for (int step = 32; step > 0; step >>= 1) {
        int ca = a + step;
        if (ca <= 60 && kf[ca + 3] <= t) a = ca;
    }
    return a;
}

__global__ __launch_bounds__(THREADS)
void bspline_loss_fused(const float* __restrict__ pred,
                        const float* __restrict__ tru,
                        float* __restrict__ out)
{
    __shared__ float  s_kf [2][ROWS_PER_BLOCK][KF_LEN];
    __shared__ float2 s_cxy[2][ROWS_PER_BLOCK][CXY_LEN];

    // Zero kf padding with STS.128: 16 (tensor,row) pairs, 1 float4 each.
    if (threadIdx.x < 2 * ROWS_PER_BLOCK) {
        int tsel = threadIdx.x >> 3;
        int r    = threadIdx.x & 7;
        *reinterpret_cast<float4*>(&s_kf[tsel][r][0]) = make_float4(0.f, 0.f, 0.f, 0.f);
    }

    // Wide transpose: 1 work item = 4 triples = 3 LDG.128 in, 3 STS.128 out.
    // G = 2 tensors x 8 rows x 16 groups = 256 items.
    {
        const size_t base = (size_t)blockIdx.x * ROWS_PER_BLOCK * ROW_FLOATS;
        const float4* gp = reinterpret_cast<const float4*>(pred + base);
        const float4* gt = reinterpret_cast<const float4*>(tru + base);
        const int G = 2 * ROWS_PER_BLOCK * 16;
        for (int g = threadIdx.x; g < G; g += THREADS) {
            const int tsel = g >> 7;           // 0..1
            const int r    = (g >> 4) & 7;     // 0..7
            const int grp  = g & 15;           // 0..15 -> elements 4*grp..4*grp+3
            const float4* src = tsel ? gt : gp;
            const int idx4 = 48 * r + 3 * grp;
            float4 v0 = src[idx4 + 0];   // k0 x0 y0 k1
            float4 v1 = src[idx4 + 1];   // x1 y1 k2 x2
            float4 v2 = src[idx4 + 2];   // y2 k3 x3 y3
            const int i = 4 * grp;
            // knots: kf[4+i .. 4+i+3], 16B-aligned (4+i ≡ 0 mod 4, row stride 272B)
            *reinterpret_cast<float4*>(&s_kf[tsel][r][4 + i]) =
                make_float4(v0.x, v0.w, v1.z, v2.y);
            // coeffs: cxy[i..i+3] as two float4 (row stride 528B, i even)
            float4* cdst = reinterpret_cast<float4*>(&s_cxy[tsel][r][i]);
            cdst[0] = make_float4(v0.y, v0.z, v1.x, v1.y);
            cdst[1] = make_float4(v1.w, v2.x, v2.z, v2.w);
        }
    }
    __syncthreads();

    const int row = threadIdx.x / SAMPLES;
    const int j   = threadIdx.x % SAMPLES;

    const float*  kp = &s_kf [0][row][0];
    const float*  kt = &s_kf [1][row][0];
    const float2* cp = &s_cxy[0][row][0];
    const float2* ct = &s_cxy[1][row][0];

    const float frac = (float)j / 19.0f;
    const float tp = frac * kp[64];            // high = knots[60] = kf[64], low = 0
    const float tt = frac * kt[64];

    const int i0p = knot_search(kp, tp);
    const int i0t = knot_search(kt, tt);

    float pxv, pyv, txv, tyv;
    deboor_eval(kp, cp, tp, i0p, pxv, pyv);
    deboor_eval(kt, ct, tt, i0t, txv, tyv);

    float dx = pxv - txv;
    float dy = pyv - tyv;
    float val = fmaf(dx, dx, dy * dy);

    // Warp reduce (5 full warps).
#pragma unroll
    for (int o = 16; o > 0; o >>= 1)
        val += __shfl_down_sync(0xFFFFFFFFu, val, o);

    __shared__ float warpsum[THREADS / 32];
    const int wid  = threadIdx.x >> 5;
    const int lane = threadIdx.x & 31;
    if (lane == 0) warpsum[wid] = val;
    __syncthreads();

    if (threadIdx.x == 0) {
        double tot = 0.0;
#pragma unroll
        for (int w = 0; w < THREADS / 32; w++) tot += (double)warpsum[w];
        atomicAdd(&g_sum, tot);
        __threadfence();
        unsigned int ticket = atomicAdd(&g_count, 1u);
        if (ticket == NBLOCKS - 1) {
            out[0] = (float)(g_sum / (double)((long long)B_TOTAL * SAMPLES));
            g_sum = 0.0;
            __threadfence();
            g_count = 0u;
        }
    }
}

extern "C" void kernel_launch(void* const* d_in, const int* in_sizes, int n_in,
                              void* d_out, int out_size)
{
    const float* pred = (const float*)d_in[0];
    const float* tru  = (const float*)d_in[1];
    float* out = (float*)d_out;

    bspline_loss_fused<<<NBLOCKS, THREADS>>>(pred, tru, out);
}